// round 1
// baseline (speedup 1.0000x reference)
#include <cuda_runtime.h>
#include <cuda_bf16.h>

// Problem constants
#define BDIM  2
#define NNODE 4096
#define FIN   256
#define NH    8
#define HD    32
#define HDIM  256          // NH*HD
#define GSLOPE 0.2f

// Attention tiling
#define TI 16              // i rows per CTA
#define JT 32              // j chunk
#define SWPAD 18           // padded inner dim of w tile (even -> 8B aligned, 2-way bank conflict only)

// Scratch (device globals: no allocation allowed)
__device__ float g_Wh[(size_t)BDIM*NNODE*HDIM];   // 8 MB
__device__ float g_s1[(size_t)BDIM*NNODE*NH];
__device__ float g_s2[(size_t)BDIM*NNODE*NH];

// ---------------------------------------------------------------------------
// packed fp32x2 FMA (sm_100a): d.lo += a.lo*b.lo ; d.hi += a.hi*b.hi
__device__ __forceinline__ void ffma2(unsigned long long& d, unsigned long long a, unsigned long long b) {
    asm("fma.rn.f32x2 %0, %1, %2, %3;" : "=l"(d) : "l"(a), "l"(b), "l"(d));
}
__device__ __forceinline__ unsigned long long pack2(float x) {
    unsigned long long r;
    asm("mov.b64 %0, {%1, %2};" : "=l"(r) : "f"(x), "f"(x));
    return r;
}

// ---------------------------------------------------------------------------
// Kernel 1: Wh = h @ W    (M=8192, K=256, N=256), fp32 tiled
__global__ __launch_bounds__(256) void gemm_kernel(const float* __restrict__ A,
                                                   const float* __restrict__ Bm) {
    __shared__ float As[16][64];
    __shared__ float Bs[16][64];
    int t = threadIdx.x;
    int tx = t & 15, ty = t >> 4;
    int row0 = blockIdx.y * 64;
    int col0 = blockIdx.x * 64;
    float acc[4][4] = {};
    int idx = t * 4;
    for (int k0 = 0; k0 < FIN; k0 += 16) {
        {   // A tile 64x16, store transposed
            int m = idx >> 4;
            int k = idx & 15;
            float4 v = *reinterpret_cast<const float4*>(&A[(size_t)(row0 + m) * FIN + k0 + k]);
            As[k + 0][m] = v.x; As[k + 1][m] = v.y; As[k + 2][m] = v.z; As[k + 3][m] = v.w;
        }
        {   // B tile 16x64
            int k = idx >> 6;
            int n = idx & 63;
            *reinterpret_cast<float4*>(&Bs[k][n]) =
                *reinterpret_cast<const float4*>(&Bm[(size_t)(k0 + k) * HDIM + col0 + n]);
        }
        __syncthreads();
#pragma unroll
        for (int k = 0; k < 16; k++) {
            float4 a4 = *reinterpret_cast<const float4*>(&As[k][ty * 4]);
            float4 b4 = *reinterpret_cast<const float4*>(&Bs[k][tx * 4]);
            float av[4] = {a4.x, a4.y, a4.z, a4.w};
            float bv[4] = {b4.x, b4.y, b4.z, b4.w};
#pragma unroll
            for (int i = 0; i < 4; i++)
#pragma unroll
                for (int j = 0; j < 4; j++) acc[i][j] += av[i] * bv[j];
        }
        __syncthreads();
    }
#pragma unroll
    for (int i = 0; i < 4; i++) {
        float4 v = make_float4(acc[i][0], acc[i][1], acc[i][2], acc[i][3]);
        *reinterpret_cast<float4*>(&g_Wh[(size_t)(row0 + ty * 4 + i) * HDIM + col0 + tx * 4]) = v;
    }
}

// ---------------------------------------------------------------------------
// Kernel 2: s1[bn,h] = <Wh[bn, h*32: ], a[h, :32]> ; s2 uses a[h, 32:64]
__global__ __launch_bounds__(256) void s_kernel(const float* __restrict__ a) {
    int gw = (blockIdx.x * blockDim.x + threadIdx.x) >> 5;   // row 0..8191
    int lane = threadIdx.x & 31;
    if (gw >= BDIM * NNODE) return;
    const float* row = g_Wh + (size_t)gw * HDIM;
#pragma unroll
    for (int h = 0; h < NH; h++) {
        float v  = row[h * HD + lane];
        float p1 = v * a[h * (2 * HD) + lane];
        float p2 = v * a[h * (2 * HD) + HD + lane];
#pragma unroll
        for (int off = 16; off; off >>= 1) {
            p1 += __shfl_xor_sync(0xffffffffu, p1, off);
            p2 += __shfl_xor_sync(0xffffffffu, p2, off);
        }
        if (lane == 0) {
            g_s1[gw * NH + h] = p1;
            g_s2[gw * NH + h] = p2;
        }
    }
}

// ---------------------------------------------------------------------------
// Kernel 3: fused masked-softmax attention + PV + ELU.
// Grid: BDIM * (NNODE/TI) blocks, 256 threads.
// No max-subtraction needed (logits bounded; see analysis).
#define SM_WH   0                              // JT*HDIM        = 8192 floats
#define SM_W    (SM_WH + JT*HDIM)              // NH*JT*SWPAD    = 4608
#define SM_SI   (SM_W + NH*JT*SWPAD)           // TI*NH          = 128
#define SM_SJ   (SM_SI + TI*NH)                // NH*JT          = 256 (transposed [h][jj])
#define SM_DEN  (SM_SJ + NH*JT)                // TI*NH          = 128
#define SM_FLOATS (SM_DEN + TI*NH)             // 13312 floats = 53248 bytes

__global__ __launch_bounds__(256) void attn_kernel(const int* __restrict__ adj,
                                                   float* __restrict__ out) {
    extern __shared__ float sm[];
    float* sWh  = sm + SM_WH;
    float* sw   = sm + SM_W;
    float* sis  = sm + SM_SI;
    float* sjs  = sm + SM_SJ;
    float* sden = sm + SM_DEN;

    const int t    = threadIdx.x;
    const int b    = blockIdx.x >> 8;            // NNODE/TI = 256 tiles per batch
    const int i0   = (blockIdx.x & 255) * TI;
    const int lane = t & 31;

    // phase A mapping
    const int jj = t & 31;
    const int ib = t >> 5;                       // warp id = i base
    // phase B mapping
    const int h = t >> 5;
    const int d = t & 31;

    union { unsigned long long u[TI / 2]; float f[TI]; } acc;
#pragma unroll
    for (int p = 0; p < TI / 2; p++) acc.u[p] = 0ull;
    float dp[2][NH];
#pragma unroll
    for (int q = 0; q < 2; q++)
#pragma unroll
        for (int hh = 0; hh < NH; hh++) dp[q][hh] = 0.f;

    if (t < TI * NH)
        sis[t] = g_s1[(size_t)(b * NNODE + i0 + (t >> 3)) * NH + (t & 7)];

    const size_t adj_base = ((size_t)b * NNODE + i0) * NNODE;
    const float4* Wh4b = reinterpret_cast<const float4*>(g_Wh + (size_t)b * NNODE * HDIM);

    for (int j0 = 0; j0 < NNODE; j0 += JT) {
        // ---- stage Wh[j0:j0+JT, :] and s_j chunk
        {
            const float4* src = Wh4b + (size_t)j0 * (HDIM / 4);
            float4* dst = reinterpret_cast<float4*>(sWh);
#pragma unroll
            for (int r = 0; r < (JT * HDIM / 4) / 256; r++)
                dst[t + r * 256] = src[t + r * 256];
            // s_j transposed: sjs[h*JT + j]
            int jv = t >> 3, hh = t & 7;
            sjs[hh * JT + jv] = g_s2[(size_t)(b * NNODE + j0 + jv) * NH + hh];
        }
        __syncthreads();

        // ---- phase A: weights w = adj * exp(lrelu(s_i + s_j)) for all (i,h,jj)
#pragma unroll
        for (int q = 0; q < 2; q++) {
            int ii = ib + q * 8;
            int adjv = adj[adj_base + (size_t)ii * NNODE + j0 + jj];
#pragma unroll
            for (int hh = 0; hh < NH; hh++) {
                float e = sis[ii * NH + hh] + sjs[hh * JT + jj];
                e = fmaxf(e, GSLOPE * e);
                float ex = __expf(e);
                float w = adjv ? ex : 0.0f;
                sw[(hh * JT + jj) * SWPAD + ii] = w;
                dp[q][hh] += w;
            }
        }
        __syncthreads();

        // ---- phase B: acc[i] += w[i,h,jj] * Wh[jj, h*32+d]  (packed f32x2)
#pragma unroll 4
        for (int j = 0; j < JT; j++) {
            float whv = sWh[j * HDIM + (h << 5) + d];
            unsigned long long whv2 = pack2(whv);
            const unsigned long long* wp =
                reinterpret_cast<const unsigned long long*>(&sw[(h * JT + j) * SWPAD]);
#pragma unroll
            for (int p = 0; p < TI / 2; p++) ffma2(acc.u[p], wp[p], whv2);
        }
        __syncthreads();
    }

    // ---- denominators: warp-reduce dp over lanes (lanes = jj slices)
#pragma unroll
    for (int q = 0; q < 2; q++)
#pragma unroll
        for (int hh = 0; hh < NH; hh++) {
            float v = dp[q][hh];
#pragma unroll
            for (int off = 16; off; off >>= 1) v += __shfl_xor_sync(0xffffffffu, v, off);
            if (lane == 0) sden[(ib + q * 8) * NH + hh] = v;
        }
    __syncthreads();

    // ---- epilogue: divide + ELU, coalesced store
#pragma unroll
    for (int i = 0; i < TI; i++) {
        float x = acc.f[i] / sden[i * NH + h];
        x = x > 0.f ? x : expm1f(x);
        out[(size_t)(b * NNODE + i0 + i) * HDIM + t] = x;
    }
}

// ---------------------------------------------------------------------------
extern "C" void kernel_launch(void* const* d_in, const int* in_sizes, int n_in,
                              void* d_out, int out_size) {
    const float* h   = (const float*)d_in[0];
    const int*   adj = (const int*)d_in[1];
    const float* W   = (const float*)d_in[2];
    const float* a   = (const float*)d_in[3];
    float* out = (float*)d_out;

    // 1) Wh = h @ W
    gemm_kernel<<<dim3(HDIM / 64, (BDIM * NNODE) / 64), 256>>>(h, W);
    // 2) attention logit projections
    s_kernel<<<(BDIM * NNODE * 32) / 256, 256>>>(a);
    // 3) fused attention
    cudaFuncSetAttribute(attn_kernel, cudaFuncAttributeMaxDynamicSharedMemorySize,
                         SM_FLOATS * sizeof(float));
    attn_kernel<<<BDIM * (NNODE / TI), 256, SM_FLOATS * sizeof(float)>>>(adj, out);
}